// round 12
// baseline (speedup 1.0000x reference)
#include <cuda_runtime.h>
#include <cuda_bf16.h>
#include <cstdint>

// ============================================================================
// IsingRBM: psi[m] = prod_h cos(bias[h] + (x@W1)[m,h] + 0.5 * x^T W2[h] x)
// mma.sync.m16n8k16 bf16 (compute_103 baseline PTX; tcgen05 unavailable).
//
// R12: jo-major 8-granular packing -> ONE small chunk template per octet.
//  * K halves regrouped: group jo=j holds rows 0..8j+7 (row i appears once
//    in every group j >= i>>3 — same folded weights, same K=2368, 37 chunks).
//    Chunk (j, n) = rows 8n..8n+7, octet j. A-register index = compile-time
//    J; row scale index = runtime ibase+2KB(+1). Mainloop code shrinks from
//    ~148 KB (R11 full unroll; I$-thrash with drifting warps) to ~12 KB.
//  * B in MMA fragment order -> 2 LDG.128/kb, register double-buffer,
//    NO smem staging, NO barriers in the loop (R11).
//  * linear chunk: scale = 1 -> A fragments used directly, zero HMUL2.
// ============================================================================

static constexpr int kV = 64;
static constexpr int kH = 128;
static constexpr int kMTile = 128;
static constexpr int kChunks = 37;                 // 36 quadratic + 1 linear
static constexpr int kChunkBytes = kH * kV * 2;    // 16384
static constexpr int kThreads = 512;

// smem layout (bytes, relative to 1024-aligned base)
static constexpr int SM_BIAS = 0;                  // 128 f32 = 512
static constexpr int SM_PART = 512;                // 128*4 f32 = 2048
static constexpr int SM_XQ   = 2560;               // 64 j * 32 grp * 4 t u32 = 32768
static constexpr int SM_XT   = 36864;              // 1024-aligned, 16384
static constexpr int SM_END  = SM_XT + 16384;      // 53248
static constexpr int SMEM_TOTAL = SM_END + 1024;

// Fragment-ordered B operand: [c][W(4)][kb(4)][q(2)][lane(32)][16B]
__device__ __align__(16) unsigned char g_wb[kChunks * kChunkBytes];

// ---------------------------------------------------------------------------
// helpers
// ---------------------------------------------------------------------------
__device__ __forceinline__ uint32_t smem_u32(const void* p) {
    uint32_t a;
    asm("{ .reg .u64 t; cvta.to.shared.u64 t, %1; cvt.u32.u64 %0, t; }"
        : "=r"(a) : "l"(p));
    return a;
}

#define SW128(o) ((o) ^ (((o) >> 3) & 0x70))

#define CVT_BF16X2(result, a, b) \
    asm("cvt.rn.bf16x2.f32 %0, %1, %2;" : "=r"(result) : "f"(b), "f"(a))

#define HMUL2(d, a, b) \
    asm("mul.rn.bf16x2 %0, %1, %2;" : "=r"(d) : "r"(a), "r"(b))

#define LDSM_X4(r0, r1, r2, r3, addr) \
    asm volatile("ldmatrix.sync.aligned.m8n8.x4.shared.b16 {%0,%1,%2,%3}, [%4];" \
        : "=r"(r0), "=r"(r1), "=r"(r2), "=r"(r3) : "r"(addr))

#define MMA16816(d, a0, a1, a2, a3, b0, b1) \
    asm volatile("mma.sync.aligned.m16n8k16.row.col.f32.bf16.bf16.f32 " \
        "{%0,%1,%2,%3}, {%4,%5,%6,%7}, {%8,%9}, {%0,%1,%2,%3};" \
        : "+f"((d)[0]), "+f"((d)[1]), "+f"((d)[2]), "+f"((d)[3]) \
        : "r"(a0), "r"(a1), "r"(a2), "r"(a3), "r"(b0), "r"(b1))

__device__ __forceinline__ float cos_poly(float a) {
    // |a| < 0.1 guaranteed by problem statistics; deg-8 Taylor, err < 1e-12
    float t = a * a;
    return 1.0f + t * (-0.5f + t * (4.16666667e-2f +
               t * (-1.38888889e-3f + t * 2.48015873e-5f)));
}

// ---------------------------------------------------------------------------
// prep: one CTA per h. Stage W2[h] in smem (coalesced), emit folded weights
// in per-thread fragment order, jo-major chunk schedule.
// chunk c (c < 36): j = group octet (T(j)=j(j+1)/2 <= c < T(j+1)), n = c-T(j);
//   half h' of chunk -> row 8n+h', column octet j.  c == 36: linear (2*W1^T).
// fragment uint2 index = c*2048 + kb*128 + t*2
//                      + [W*512 + (nbk>>1)*64 + lrow*8 + (nbk&1)]
//   with W = h>>5, nbk = (h>>3)&3, lrow = h&7 (unchanged from R11, verified).
// ---------------------------------------------------------------------------
__global__ void __launch_bounds__(256) prep_kernel(const float* __restrict__ w2,
                                                   const float* __restrict__ w1) {
    __shared__ float sw[4096];
    const int h = blockIdx.x;
    const float4* src = reinterpret_cast<const float4*>(w2 + (size_t)h * 4096);
    #pragma unroll
    for (int e = threadIdx.x; e < 1024; e += 256)
        reinterpret_cast<float4*>(sw)[e] = src[e];
    __syncthreads();

    const int W = h >> 5, nbk = (h >> 3) & 3, lrow = h & 7;
    const int hbase = W * 512 + (nbk >> 1) * 64 + lrow * 8 + (nbk & 1);
    uint2* dst = reinterpret_cast<uint2*>(g_wb);

    // 37 chunks * 4 kb * 4 t = 592 uint2 outputs for this h
    for (int idx = threadIdx.x; idx < kChunks * 16; idx += 256) {
        int c  = idx >> 4;
        int r  = idx & 15;
        int kb = r >> 2;
        int t  = r & 3;
        int j = 0;
        while ((j + 1) * (j + 2) / 2 <= c && j < 7) j++;   // octet group
        int n = c - j * (j + 1) / 2;
        float v[4];
        #pragma unroll
        for (int q = 0; q < 4; q++) {
            int klocal = (q < 2) ? (2 * t + q) : (2 * t + 6 + q);  // 2t,2t+1,2t+8,2t+9
            if (c == 36) {                       // linear chunk
                int jc = kb * 16 + klocal;
                v[q] = 2.0f * w1[jc * kH + h];
            } else {
                int half = kb * 2 + (klocal >> 3);
                int i    = 8 * n + half;
                int jc   = 8 * j + (klocal & 7);
                if (jc > i)       v[q] = sw[i * 64 + jc] + sw[jc * 64 + i];
                else if (jc == i) v[q] = sw[i * 64 + jc];
                else              v[q] = 0.0f;   // below-diagonal padding
            }
        }
        uint32_t lo, hi;
        CVT_BF16X2(lo, v[0], v[1]);
        CVT_BF16X2(hi, v[2], v[3]);
        dst[c * 2048 + kb * 128 + t * 2 + hbase] = make_uint2(lo, hi);
    }
}

// ---------------------------------------------------------------------------
// one k16 block: octet J compile-time, rows ibase+2KB, ibase+2KB+1 runtime.
// Consumes bfr[KB] (chunk at gBc), prefetches next chunk's KB fragments.
// ---------------------------------------------------------------------------
template<int J, int KB>
__device__ __forceinline__ void do_kb(
    const uint4* __restrict__ gBc, uint4 (&bfr)[4][2],
    const uint32_t (&ab)[2][8][2], const uint4* __restrict__ xq4p,
    int ibase, float (&acc)[2][4][4])
{
    uint4 s0 = xq4p[(ibase + 2 * KB) * 32];
    uint4 s1 = xq4p[(ibase + 2 * KB + 1) * 32];
    const uint4 lo = bfr[KB][0], hi = bfr[KB][1];
    bfr[KB][0] = gBc[1024 + KB * 64];          // prefetch next chunk's KB
    bfr[KB][1] = gBc[1024 + KB * 64 + 32];
    const uint32_t sv0[4] = { s0.x, s0.y, s0.z, s0.w };
    const uint32_t sv1[4] = { s1.x, s1.y, s1.z, s1.w };
    #pragma unroll
    for (int mb = 0; mb < 2; mb++) {
        uint32_t t0, t1, t2, t3;
        HMUL2(t0, ab[mb][J][0], sv0[2 * mb]);      // rows g,   k 0-7
        HMUL2(t1, ab[mb][J][1], sv0[2 * mb + 1]);  // rows g+8, k 0-7
        HMUL2(t2, ab[mb][J][0], sv1[2 * mb]);      // rows g,   k 8-15
        HMUL2(t3, ab[mb][J][1], sv1[2 * mb + 1]);  // rows g+8, k 8-15
        MMA16816(acc[mb][0], t0, t1, t2, t3, lo.x, lo.y);
        MMA16816(acc[mb][1], t0, t1, t2, t3, lo.z, lo.w);
        MMA16816(acc[mb][2], t0, t1, t2, t3, hi.x, hi.y);
        MMA16816(acc[mb][3], t0, t1, t2, t3, hi.z, hi.w);
    }
}

// linear chunk (scale = 1): A fragments used directly, no prefetch (last).
template<int KB>
__device__ __forceinline__ void do_kb_lin(
    uint4 (&bfr)[4][2], const uint32_t (&ab)[2][8][2], float (&acc)[2][4][4])
{
    const uint4 lo = bfr[KB][0], hi = bfr[KB][1];
    #pragma unroll
    for (int mb = 0; mb < 2; mb++) {
        uint32_t t0 = ab[mb][2 * KB][0],     t1 = ab[mb][2 * KB][1];
        uint32_t t2 = ab[mb][2 * KB + 1][0], t3 = ab[mb][2 * KB + 1][1];
        MMA16816(acc[mb][0], t0, t1, t2, t3, lo.x, lo.y);
        MMA16816(acc[mb][1], t0, t1, t2, t3, lo.z, lo.w);
        MMA16816(acc[mb][2], t0, t1, t2, t3, hi.x, hi.y);
        MMA16816(acc[mb][3], t0, t1, t2, t3, hi.z, hi.w);
    }
}

// ---------------------------------------------------------------------------
// main fused kernel: 128-row M-tile per CTA, H=128 as N, 16 warps (4M x 4N),
// 1 CTA per SM, no barriers in the main loop, ~12 KB loop body
// ---------------------------------------------------------------------------
__global__ void __launch_bounds__(kThreads, 1)
rbm_main_kernel(const float* __restrict__ x,
                const float* __restrict__ bias,
                float* __restrict__ out) {
    extern __shared__ char smem_raw[];
    char* sm = (char*)((((uintptr_t)smem_raw) + 1023) & ~(uintptr_t)1023);
    const uint32_t sb = smem_u32(sm);
    const int tid = threadIdx.x;
    const int l   = tid & 31;
    const int w   = tid >> 5;
    const int g   = l >> 2;
    const int t4  = l & 3;
    const int wm  = (w >> 2) * 32;     // warp M offset (0,32,64,96)
    const int wn  = (w & 3) * 32;      // warp N offset (0,32,64,96)
    const int m0  = blockIdx.x * kMTile;

    float*    sbias = (float*)(sm + SM_BIAS);
    float*    spart = (float*)(sm + SM_PART);     // [m][4 wn-groups]
    uint32_t* xq    = (uint32_t*)(sm + SM_XQ);    // [j][32 grp][4 t] u32

    if (tid < kH) sbias[tid] = bias[tid];

    // --- x bf16 tile [m][j], 128B rows, SW128 swizzled (A ldmatrix source) ---
    {
        const float4* x4 = (const float4*)(x + (size_t)m0 * kV);
        #pragma unroll
        for (int e = tid; e < kMTile * 16; e += kThreads) {   // 128 rows * 16 f4
            int r = e >> 4, q = e & 15;
            float4 f = x4[e];
            uint32_t u0, u1;
            CVT_BF16X2(u0, f.x, f.y);
            CVT_BF16X2(u1, f.z, f.w);
            uint32_t off = (uint32_t)(r * 128 + q * 8);
            *(uint2*)(sm + SM_XT + SW128(off)) = make_uint2(u0, u1);
        }
    }
    // --- xq[j][grp][t] = bf16x2 broadcast of x[m0 + (grp>>3)*32 + (grp&7) + 8t][j]
    #pragma unroll
    for (int e = tid; e < kV * 32 * 4; e += kThreads) {   // 8192 entries
        int j   = e >> 7;
        int grp = (e >> 2) & 31;
        int t   = e & 3;
        int m   = (grp >> 3) * 32 + (grp & 7) + 8 * t;
        float v = x[(size_t)(m0 + m) * kV + j];
        uint32_t p;
        CVT_BF16X2(p, v, v);
        xq[e] = p;
    }

    // --- per-thread fragment pointer into g_wb (uint4 units) ---
    const uint4* gB = reinterpret_cast<const uint4*>(g_wb) + (w & 3) * 256 + l;

    // --- prologue: chunk 0 fragments into registers ---
    uint4 bfr[4][2];
    #pragma unroll
    for (int kb = 0; kb < 4; kb++) {
        bfr[kb][0] = gB[kb * 64];
        bfr[kb][1] = gB[kb * 64 + 32];
    }

    __syncthreads();   // x tiles + bias ready (only barrier before epilogue)

    // --- A-base fragments (warp's 32x64 x-tile) in registers, octet-indexed ---
    uint32_t ab[2][8][2];
    {
        int q = l >> 3, rr = l & 7;
        #pragma unroll
        for (int mb = 0; mb < 2; mb++)
        #pragma unroll
        for (int kb = 0; kb < 4; kb++) {
            uint32_t off = (uint32_t)((wm + 16 * mb + (q & 1) * 8 + rr) * 128
                                      + (kb * 16 + (q >> 1) * 8) * 2);
            LDSM_X4(ab[mb][2 * kb][0], ab[mb][2 * kb][1],
                    ab[mb][2 * kb + 1][0], ab[mb][2 * kb + 1][1],
                    sb + SM_XT + SW128(off));
        }
    }

    float acc[2][4][4];
    #pragma unroll
    for (int a = 0; a < 2; a++)
    #pragma unroll
    for (int b = 0; b < 4; b++)
    #pragma unroll
    for (int c = 0; c < 4; c++) acc[a][b][c] = 0.0f;

    const int rb0 = wm + g;
    const uint4* xq4p = reinterpret_cast<const uint4*>(xq) + ((wm >> 2) + g);
    const uint4* gBc = gB;

    // --- jo-major mainloop: group j has j+1 chunks (rows 8n..8n+7, octet j) ---
    #define RUN_J(J)                                                          \
        _Pragma("unroll 1")                                                   \
        for (int n = 0; n <= (J); n++) {                                      \
            do_kb<J, 0>(gBc, bfr, ab, xq4p, 8 * n, acc);                      \
            do_kb<J, 1>(gBc, bfr, ab, xq4p, 8 * n, acc);                      \
            do_kb<J, 2>(gBc, bfr, ab, xq4p, 8 * n, acc);                      \
            do_kb<J, 3>(gBc, bfr, ab, xq4p, 8 * n, acc);                      \
            gBc += 1024;                                                      \
        }
    RUN_J(0) RUN_J(1) RUN_J(2) RUN_J(3) RUN_J(4) RUN_J(5) RUN_J(6) RUN_J(7)
    #undef RUN_J

    // linear chunk (c = 36): fragments already in bfr via last prefetch
    do_kb_lin<0>(bfr, ab, acc);
    do_kb_lin<1>(bfr, ab, acc);
    do_kb_lin<2>(bfr, ab, acc);
    do_kb_lin<3>(bfr, ab, acc);

    // --- epilogue: a = bias + 0.5*acc; psi = prod cos(a) ---
    #pragma unroll
    for (int mb = 0; mb < 2; mb++) {
        float p0 = 1.0f, p1 = 1.0f;
        #pragma unroll
        for (int nb = 0; nb < 4; nb++) {
            int col = wn + nb * 8 + 2 * t4;
            #pragma unroll
            for (int cc = 0; cc < 2; cc++) {
                float bv = sbias[col + cc];
                p0 *= cos_poly(bv + 0.5f * acc[mb][nb][cc]);       // row g
                p1 *= cos_poly(bv + 0.5f * acc[mb][nb][2 + cc]);   // row g+8
            }
        }
        p0 *= __shfl_xor_sync(0xFFFFFFFFu, p0, 1);
        p0 *= __shfl_xor_sync(0xFFFFFFFFu, p0, 2);
        p1 *= __shfl_xor_sync(0xFFFFFFFFu, p1, 1);
        p1 *= __shfl_xor_sync(0xFFFFFFFFu, p1, 2);
        if (t4 == 0) {
            spart[(rb0 + 16 * mb) * 4 + (w & 3)]     = p0;
            spart[(rb0 + 16 * mb + 8) * 4 + (w & 3)] = p1;
        }
    }
    __syncthreads();
    if (tid < kMTile) {
        out[m0 + tid] = spart[tid * 4 + 0] * spart[tid * 4 + 1]
                      * spart[tid * 4 + 2] * spart[tid * 4 + 3];
    }
}

// ---------------------------------------------------------------------------
// launch
// ---------------------------------------------------------------------------
extern "C" void kernel_launch(void* const* d_in, const int* in_sizes, int n_in,
                              void* d_out, int out_size) {
    const float* x    = (const float*)d_in[0];   // (16384, 64)
    const float* w1   = (const float*)d_in[1];   // (64, 128)
    const float* w2   = (const float*)d_in[2];   // (128, 64, 64)
    const float* bias = (const float*)d_in[3];   // (128,)
    float* out = (float*)d_out;                  // (16384,)

    cudaFuncSetAttribute(rbm_main_kernel,
                         cudaFuncAttributeMaxDynamicSharedMemorySize, SMEM_TOTAL);

    prep_kernel<<<kH, 256>>>(w2, w1);            // one CTA per h
    rbm_main_kernel<<<16384 / kMTile, kThreads, SMEM_TOTAL>>>(x, bias, out);
}

// round 13
// speedup vs baseline: 1.0007x; 1.0007x over previous
#include <cuda_runtime.h>
#include <cuda_bf16.h>
#include <cstdint>

// ============================================================================
// IsingRBM: psi[m] = prod_h cos(bias[h] + (x@W1)[m,h] + 0.5 * x^T W2[h] x)
// mma.sync.m16n8k16 bf16 (compute_103 baseline PTX; tcgen05 unavailable).
//
// R13: warp grid 2M x 8N (warp tile 64M x 16N) with jo-major on-demand A.
//  * B-fragment duplication across warps drops 4x -> 2x (halved B LDG).
//  * jo-major schedule: group J (octet J) has J+1 chunks (rows 8n..8n+7).
//    Only octets (J, J+1) of A live at a time: ab = 16 regs, reloaded by
//    4 LDSM.x4 at each J-pair boundary (4 reloads total). This is what made
//    R7's 2Mx8N spill (64-reg ab at the 128 cap) — now ~95 regs total.
//  * B in MMA fragment order -> 1 LDG.128 per kb per warp, register
//    double-buffer one chunk ahead, NO smem staging, NO loop barriers (R11).
//  * linear chunk (c=36): scale=1, A straight from XT via LDSM.
// ============================================================================

static constexpr int kV = 64;
static constexpr int kH = 128;
static constexpr int kMTile = 128;
static constexpr int kChunks = 37;                 // 36 quadratic + 1 linear
static constexpr int kChunkBytes = kH * kV * 2;    // 16384
static constexpr int kThreads = 512;

// smem layout (bytes, relative to 1024-aligned base)
static constexpr int SM_BIAS = 0;                  // 128 f32 = 512
static constexpr int SM_PART = 512;                // 128*8 f32 = 4096
static constexpr int SM_XQ   = 4608;               // 64 i * 128 u32 = 32768
static constexpr int SM_XT   = 37888;              // 1024-aligned, 16384
static constexpr int SM_END  = SM_XT + 16384;      // 54272
static constexpr int SMEM_TOTAL = SM_END + 1024;

// Fragment-ordered B operand: [c][W(8)][kb(4)][lane(32)][16B]
__device__ __align__(16) unsigned char g_wb[kChunks * kChunkBytes];

// ---------------------------------------------------------------------------
// helpers
// ---------------------------------------------------------------------------
__device__ __forceinline__ uint32_t smem_u32(const void* p) {
    uint32_t a;
    asm("{ .reg .u64 t; cvta.to.shared.u64 t, %1; cvt.u32.u64 %0, t; }"
        : "=r"(a) : "l"(p));
    return a;
}

#define SW128(o) ((o) ^ (((o) >> 3) & 0x70))

#define CVT_BF16X2(result, a, b) \
    asm("cvt.rn.bf16x2.f32 %0, %1, %2;" : "=r"(result) : "f"(b), "f"(a))

#define HMUL2(d, a, b) \
    asm("mul.rn.bf16x2 %0, %1, %2;" : "=r"(d) : "r"(a), "r"(b))

#define LDSM_X4(r0, r1, r2, r3, addr) \
    asm volatile("ldmatrix.sync.aligned.m8n8.x4.shared.b16 {%0,%1,%2,%3}, [%4];" \
        : "=r"(r0), "=r"(r1), "=r"(r2), "=r"(r3) : "r"(addr))

#define MMA16816(d, a0, a1, a2, a3, b0, b1) \
    asm volatile("mma.sync.aligned.m16n8k16.row.col.f32.bf16.bf16.f32 " \
        "{%0,%1,%2,%3}, {%4,%5,%6,%7}, {%8,%9}, {%0,%1,%2,%3};" \
        : "+f"((d)[0]), "+f"((d)[1]), "+f"((d)[2]), "+f"((d)[3]) \
        : "r"(a0), "r"(a1), "r"(a2), "r"(a3), "r"(b0), "r"(b1))

__device__ __forceinline__ float cos_poly(float a) {
    // |a| < 0.1 guaranteed by problem statistics; deg-8 Taylor, err < 1e-12
    float t = a * a;
    return 1.0f + t * (-0.5f + t * (4.16666667e-2f +
               t * (-1.38888889e-3f + t * 2.48015873e-5f)));
}

// ---------------------------------------------------------------------------
// prep: one CTA per h. Stage W2[h] in smem (coalesced), emit folded weights
// in per-thread fragment order for the 8-N-group layout.
// chunk c < 36: group octet j (T(j)=j(j+1)/2 <= c < T(j+1)), n = c - T(j);
//   k16 block kb: rows 8n+2kb (k0-7), 8n+2kb+1 (k8-15), columns octet j.
// c == 36: linear (2*W1^T), column jc = kb*16 + klocal.
// Fragment placement: W = h>>4 (N-group), nbk = (h>>3)&1, lrow = h&7;
// lane = lrow*4 + t holds k-pairs (2t,2t+1) and (2t+8,2t+9);
// uint2 index = c*2048 + W*256 + kb*64 + lane*2 + nbk.
// ---------------------------------------------------------------------------
__global__ void __launch_bounds__(256) prep_kernel(const float* __restrict__ w2,
                                                   const float* __restrict__ w1) {
    __shared__ float sw[4096];
    const int h = blockIdx.x;
    const float4* src = reinterpret_cast<const float4*>(w2 + (size_t)h * 4096);
    #pragma unroll
    for (int e = threadIdx.x; e < 1024; e += 256)
        reinterpret_cast<float4*>(sw)[e] = src[e];
    __syncthreads();

    const int W = h >> 4, nbk = (h >> 3) & 1, lrow = h & 7;
    uint2* dst = reinterpret_cast<uint2*>(g_wb);

    // 37 chunks * 4 kb * 4 t = 592 uint2 outputs for this h
    for (int idx = threadIdx.x; idx < kChunks * 16; idx += 256) {
        int c  = idx >> 4;
        int r  = idx & 15;
        int kb = r >> 2;
        int t  = r & 3;
        int j = 0;
        while ((j + 1) * (j + 2) / 2 <= c && j < 7) j++;   // octet group
        int n = c - j * (j + 1) / 2;
        float v[4];
        #pragma unroll
        for (int q = 0; q < 4; q++) {
            int klocal = (q < 2) ? (2 * t + q) : (2 * t + 6 + q);  // 2t,2t+1,2t+8,2t+9
            if (c == 36) {                       // linear chunk
                int jc = kb * 16 + klocal;
                v[q] = 2.0f * w1[jc * kH + h];
            } else {
                int half = kb * 2 + (klocal >> 3);
                int i    = 8 * n + half;
                int jc   = 8 * j + (klocal & 7);
                if (jc > i)       v[q] = sw[i * 64 + jc] + sw[jc * 64 + i];
                else if (jc == i) v[q] = sw[i * 64 + jc];
                else              v[q] = 0.0f;   // below-diagonal padding
            }
        }
        uint32_t lo, hi;
        CVT_BF16X2(lo, v[0], v[1]);
        CVT_BF16X2(hi, v[2], v[3]);
        dst[c * 2048 + W * 256 + kb * 64 + (lrow * 4 + t) * 2 + nbk] =
            make_uint2(lo, hi);
    }
}

// ---------------------------------------------------------------------------
// one k16 block: ODD = J&1 selects the live octet in ab; rows via xqn.
// Per kb: 4 LDS.128 scales (quad-broadcast) + 1 LDG.128 prefetch
//       + 16 HMUL2 + 8 MMA.
// ---------------------------------------------------------------------------
template<int ODD, int KB>
__device__ __forceinline__ void do_kb(
    const uint4* __restrict__ gBc, uint4 (&bfr)[4],
    const uint32_t (&ab)[4][4], const uint32_t* __restrict__ xqn,
    float (&acc)[4][2][4])
{
    uint4 s0a = *reinterpret_cast<const uint4*>(xqn + (2 * KB) * 128);
    uint4 s0b = *reinterpret_cast<const uint4*>(xqn + (2 * KB) * 128 + 4);
    uint4 s1a = *reinterpret_cast<const uint4*>(xqn + (2 * KB + 1) * 128);
    uint4 s1b = *reinterpret_cast<const uint4*>(xqn + (2 * KB + 1) * 128 + 4);
    const uint4 b = bfr[KB];
    bfr[KB] = gBc[1024 + KB * 32];             // prefetch next chunk's KB
    const uint32_t s0[8] = { s0a.x, s0a.y, s0a.z, s0a.w,
                             s0b.x, s0b.y, s0b.z, s0b.w };
    const uint32_t s1[8] = { s1a.x, s1a.y, s1a.z, s1a.w,
                             s1b.x, s1b.y, s1b.z, s1b.w };
    #pragma unroll
    for (int mb = 0; mb < 4; mb++) {
        const uint32_t aE0 = ab[mb][ODD * 2];      // rows g,   octet J
        const uint32_t aE1 = ab[mb][ODD * 2 + 1];  // rows g+8, octet J
        uint32_t t0, t1, t2, t3;
        HMUL2(t0, aE0, s0[2 * mb]);        // k 0-7,  rows g
        HMUL2(t1, aE1, s0[2 * mb + 1]);    // k 0-7,  rows g+8
        HMUL2(t2, aE0, s1[2 * mb]);        // k 8-15, rows g
        HMUL2(t3, aE1, s1[2 * mb + 1]);    // k 8-15, rows g+8
        MMA16816(acc[mb][0], t0, t1, t2, t3, b.x, b.y);
        MMA16816(acc[mb][1], t0, t1, t2, t3, b.z, b.w);
    }
}

// ---------------------------------------------------------------------------
// main fused kernel: 128-row M-tile per CTA, H=128 as N, 16 warps (2M x 8N),
// 1 CTA per SM, no barriers in the main loop
// ---------------------------------------------------------------------------
__global__ void __launch_bounds__(kThreads, 1)
rbm_main_kernel(const float* __restrict__ x,
                const float* __restrict__ bias,
                float* __restrict__ out) {
    extern __shared__ char smem_raw[];
    char* sm = (char*)((((uintptr_t)smem_raw) + 1023) & ~(uintptr_t)1023);
    const uint32_t sb = smem_u32(sm);
    const int tid = threadIdx.x;
    const int l   = tid & 31;
    const int w   = tid >> 5;
    const int g   = l >> 2;
    const int t4  = l & 3;
    const int wm  = (w >> 3) * 64;     // warp M offset (0,64)
    const int wn  = (w & 7) * 16;      // warp N offset (0,16,...,112)
    const int m0  = blockIdx.x * kMTile;

    float*    sbias = (float*)(sm + SM_BIAS);
    float*    spart = (float*)(sm + SM_PART);     // [m][8 wn-groups]
    uint32_t* xq    = (uint32_t*)(sm + SM_XQ);    // [i][mg(2)][g(8)][t(8)] u32

    if (tid < kH) sbias[tid] = bias[tid];

    // --- x bf16 tile [m][j], 128B rows, SW128 swizzled (A ldmatrix source) ---
    {
        const float4* x4 = (const float4*)(x + (size_t)m0 * kV);
        #pragma unroll
        for (int e = tid; e < kMTile * 16; e += kThreads) {   // 128 rows * 16 f4
            int r = e >> 4, q = e & 15;
            float4 f = x4[e];
            uint32_t u0, u1;
            CVT_BF16X2(u0, f.x, f.y);
            CVT_BF16X2(u1, f.z, f.w);
            uint32_t off = (uint32_t)(r * 128 + q * 8);
            *(uint2*)(sm + SM_XT + SW128(off)) = make_uint2(u0, u1);
        }
    }
    // --- xq[i][mg][g][t] = bf16x2 bcast of x[m0 + mg*64 + (t>>1)*16 + g + (t&1)*8][i]
    #pragma unroll
    for (int e = tid; e < kV * 128; e += kThreads) {   // 8192 entries
        int i  = e >> 7;
        int r  = e & 127;
        int mg = r >> 6;
        int gg = (r >> 3) & 7;
        int t  = r & 7;
        int m  = mg * 64 + (t >> 1) * 16 + gg + (t & 1) * 8;
        float v = x[(size_t)(m0 + m) * kV + i];
        uint32_t p;
        CVT_BF16X2(p, v, v);
        xq[e] = p;
    }

    // --- per-thread fragment pointer into g_wb (uint4 units) ---
    const uint4* gB = reinterpret_cast<const uint4*>(g_wb) + (w & 7) * 128 + l;

    // --- prologue: chunk 0 fragments into registers ---
    uint4 bfr[4];
    #pragma unroll
    for (int kb = 0; kb < 4; kb++) bfr[kb] = gB[kb * 32];

    __syncthreads();   // x tiles + bias ready (only barrier before epilogue)

    float acc[4][2][4];
    #pragma unroll
    for (int a = 0; a < 4; a++)
    #pragma unroll
    for (int b = 0; b < 2; b++)
    #pragma unroll
    for (int c = 0; c < 4; c++) acc[a][b][c] = 0.0f;

    const uint32_t* xqb = xq + (w >> 3) * 64 + g * 8;   // thread scale base
    const uint4* gBc = gB;
    uint32_t ab[4][4];                                   // octets (JJ, JJ+1)
    const int q2 = l >> 3, rr = l & 7;

    // reload A for octet pair (JJ, JJ+1): ab[mb] = {J.g, J.g8, J1.g, J1.g8}
    #define RELOAD_AB(JJ) do {                                                \
        _Pragma("unroll")                                                     \
        for (int mb = 0; mb < 4; mb++) {                                      \
            uint32_t off = (uint32_t)((wm + 16 * mb + (q2 & 1) * 8 + rr) * 128\
                                      + (((JJ) >> 1) * 16 + (q2 >> 1) * 8) * 2);\
            LDSM_X4(ab[mb][0], ab[mb][1], ab[mb][2], ab[mb][3],               \
                    sb + SM_XT + SW128(off));                                 \
        }                                                                     \
    } while (0)

    #define RUN_GROUP(J)                                                      \
        _Pragma("unroll 1")                                                   \
        for (int n = 0; n <= (J); n++) {                                      \
            const uint32_t* xqn = xqb + n * 1024;                             \
            do_kb<(J) & 1, 0>(gBc, bfr, ab, xqn, acc);                        \
            do_kb<(J) & 1, 1>(gBc, bfr, ab, xqn, acc);                        \
            do_kb<(J) & 1, 2>(gBc, bfr, ab, xqn, acc);                        \
            do_kb<(J) & 1, 3>(gBc, bfr, ab, xqn, acc);                        \
            gBc += 1024;                                                      \
        }

    RELOAD_AB(0); RUN_GROUP(0) RUN_GROUP(1)
    RELOAD_AB(2); RUN_GROUP(2) RUN_GROUP(3)
    RELOAD_AB(4); RUN_GROUP(4) RUN_GROUP(5)
    RELOAD_AB(6); RUN_GROUP(6) RUN_GROUP(7)
    #undef RUN_GROUP
    #undef RELOAD_AB

    // --- linear chunk (c = 36, scale = 1): A straight from XT per kb ---
    #pragma unroll
    for (int KB = 0; KB < 4; KB++) {
        const uint4 b = bfr[KB];
        #pragma unroll
        for (int mb = 0; mb < 4; mb++) {
            uint32_t t0, t1, t2, t3;
            uint32_t off = (uint32_t)((wm + 16 * mb + (q2 & 1) * 8 + rr) * 128
                                      + (KB * 16 + (q2 >> 1) * 8) * 2);
            LDSM_X4(t0, t1, t2, t3, sb + SM_XT + SW128(off));
            MMA16816(acc[mb][0], t0, t1, t2, t3, b.x, b.y);
            MMA16816(acc[mb][1], t0, t1, t2, t3, b.z, b.w);
        }
    }

    // --- epilogue: a = bias + 0.5*acc; psi = prod cos(a) ---
    #pragma unroll
    for (int mb = 0; mb < 4; mb++) {
        float p0 = 1.0f, p1 = 1.0f;
        #pragma unroll
        for (int nb = 0; nb < 2; nb++) {
            int col = wn + nb * 8 + 2 * t4;
            #pragma unroll
            for (int cc = 0; cc < 2; cc++) {
                float bv = sbias[col + cc];
                p0 *= cos_poly(bv + 0.5f * acc[mb][nb][cc]);       // row g
                p1 *= cos_poly(bv + 0.5f * acc[mb][nb][2 + cc]);   // row g+8
            }
        }
        // quad reduce -> product over this warp's 16 cols
        p0 *= __shfl_xor_sync(0xFFFFFFFFu, p0, 1);
        p0 *= __shfl_xor_sync(0xFFFFFFFFu, p0, 2);
        p1 *= __shfl_xor_sync(0xFFFFFFFFu, p1, 1);
        p1 *= __shfl_xor_sync(0xFFFFFFFFu, p1, 2);
        if (t4 == 0) {
            int r0 = wm + 16 * mb + g;
            spart[r0 * 8 + (w & 7)]       = p0;
            spart[(r0 + 8) * 8 + (w & 7)] = p1;
        }
    }
    __syncthreads();
    if (tid < kMTile) {
        const float* sp = spart + tid * 8;
        out[m0 + tid] = ((sp[0] * sp[1]) * (sp[2] * sp[3]))
                      * ((sp[4] * sp[5]) * (sp[6] * sp[7]));
    }
}

// ---------------------------------------------------------------------------
// launch
// ---------------------------------------------------------------------------
extern "C" void kernel_launch(void* const* d_in, const int* in_sizes, int n_in,
                              void* d_out, int out_size) {
    const float* x    = (const float*)d_in[0];   // (16384, 64)
    const float* w1   = (const float*)d_in[1];   // (64, 128)
    const float* w2   = (const float*)d_in[2];   // (128, 64, 64)
    const float* bias = (const float*)d_in[3];   // (128,)
    float* out = (float*)d_out;                  // (16384,)

    cudaFuncSetAttribute(rbm_main_kernel,
                         cudaFuncAttributeMaxDynamicSharedMemorySize, SMEM_TOTAL);

    prep_kernel<<<kH, 256>>>(w2, w1);            // one CTA per h
    rbm_main_kernel<<<16384 / kMTile, kThreads, SMEM_TOTAL>>>(x, bias, out);
}

// round 14
// speedup vs baseline: 1.1041x; 1.1033x over previous
#include <cuda_runtime.h>
#include <cuda_bf16.h>
#include <cstdint>

// ============================================================================
// IsingRBM: psi[m] = prod_h cos(bias[h] + (x@W1)[m,h] + 0.5 * x^T W2[h] x)
// mma.sync.m16n8k16 bf16 (compute_103 baseline PTX; tcgen05 unavailable).
//
// R14 = R11's proven 4Mx4N shape + jo-major schedule for register slack.
//  * jo-major: chunk (J, n) = rows 8n..8n+7, column octet J; group J has
//    J+1 chunks; 36 quadratic + 1 linear = same K=2368 as R10-R13.
//  * A live set = octet pair (J, J+1) only: ab[2][4] = 8 regs (R11 kept all
//    8 octets = 32 regs at the 128-reg wall with zero scheduling slack).
//    Reloaded by 2 LDSM.x4 at each even-J boundary (4 reloads total).
//  * B in MMA fragment order (R12 prep, correctness-verified): 2 LDG.128
//    per kb, register prefetch one chunk ahead, NO smem staging, NO loop
//    barriers. ~105 regs total -> ptxas can overlap kb+1 loads under kb MMAs.
//  * linear chunk (c=36): scale=1, A straight from XT via LDSM.
// ============================================================================

static constexpr int kV = 64;
static constexpr int kH = 128;
static constexpr int kMTile = 128;
static constexpr int kChunks = 37;                 // 36 quadratic + 1 linear
static constexpr int kChunkBytes = kH * kV * 2;    // 16384
static constexpr int kThreads = 512;

// smem layout (bytes, relative to 1024-aligned base)
static constexpr int SM_BIAS = 0;                  // 128 f32 = 512
static constexpr int SM_PART = 512;                // 128*4 f32 = 2048
static constexpr int SM_XQ   = 2560;               // 64 j * 32 grp * 4 t u32 = 32768
static constexpr int SM_XT   = 36864;              // 1024-aligned, 16384
static constexpr int SM_END  = SM_XT + 16384;      // 53248
static constexpr int SMEM_TOTAL = SM_END + 1024;

// Fragment-ordered B operand: [c][W(4)][kb(4)][q(2)][lane(32)][16B]
__device__ __align__(16) unsigned char g_wb[kChunks * kChunkBytes];

// ---------------------------------------------------------------------------
// helpers
// ---------------------------------------------------------------------------
__device__ __forceinline__ uint32_t smem_u32(const void* p) {
    uint32_t a;
    asm("{ .reg .u64 t; cvta.to.shared.u64 t, %1; cvt.u32.u64 %0, t; }"
        : "=r"(a) : "l"(p));
    return a;
}

#define SW128(o) ((o) ^ (((o) >> 3) & 0x70))

#define CVT_BF16X2(result, a, b) \
    asm("cvt.rn.bf16x2.f32 %0, %1, %2;" : "=r"(result) : "f"(b), "f"(a))

#define HMUL2(d, a, b) \
    asm("mul.rn.bf16x2 %0, %1, %2;" : "=r"(d) : "r"(a), "r"(b))

#define LDSM_X4(r0, r1, r2, r3, addr) \
    asm volatile("ldmatrix.sync.aligned.m8n8.x4.shared.b16 {%0,%1,%2,%3}, [%4];" \
        : "=r"(r0), "=r"(r1), "=r"(r2), "=r"(r3) : "r"(addr))

#define MMA16816(d, a0, a1, a2, a3, b0, b1) \
    asm volatile("mma.sync.aligned.m16n8k16.row.col.f32.bf16.bf16.f32 " \
        "{%0,%1,%2,%3}, {%4,%5,%6,%7}, {%8,%9}, {%0,%1,%2,%3};" \
        : "+f"((d)[0]), "+f"((d)[1]), "+f"((d)[2]), "+f"((d)[3]) \
        : "r"(a0), "r"(a1), "r"(a2), "r"(a3), "r"(b0), "r"(b1))

__device__ __forceinline__ float cos_poly(float a) {
    // |a| < 0.1 guaranteed by problem statistics; deg-8 Taylor, err < 1e-12
    float t = a * a;
    return 1.0f + t * (-0.5f + t * (4.16666667e-2f +
               t * (-1.38888889e-3f + t * 2.48015873e-5f)));
}

// ---------------------------------------------------------------------------
// prep (verbatim R12, correctness-verified): one CTA per h; stage W2[h] in
// smem; jo-major schedule; per-thread MMA fragment order.
// chunk c < 36: octet j (T(j)=j(j+1)/2 <= c < T(j+1)), n = c - T(j);
//   k16 block kb: rows 8n+2kb (k0-7), 8n+2kb+1 (k8-15), columns octet j.
// c == 36: linear (2*W1^T).
// uint2 index = c*2048 + kb*128 + t*2 + [W*512 + (nbk>>1)*64 + lrow*8 + (nbk&1)]
//   with W = h>>5, nbk = (h>>3)&3, lrow = h&7.
// ---------------------------------------------------------------------------
__global__ void __launch_bounds__(256) prep_kernel(const float* __restrict__ w2,
                                                   const float* __restrict__ w1) {
    __shared__ float sw[4096];
    const int h = blockIdx.x;
    const float4* src = reinterpret_cast<const float4*>(w2 + (size_t)h * 4096);
    #pragma unroll
    for (int e = threadIdx.x; e < 1024; e += 256)
        reinterpret_cast<float4*>(sw)[e] = src[e];
    __syncthreads();

    const int W = h >> 5, nbk = (h >> 3) & 3, lrow = h & 7;
    const int hbase = W * 512 + (nbk >> 1) * 64 + lrow * 8 + (nbk & 1);
    uint2* dst = reinterpret_cast<uint2*>(g_wb);

    for (int idx = threadIdx.x; idx < kChunks * 16; idx += 256) {
        int c  = idx >> 4;
        int r  = idx & 15;
        int kb = r >> 2;
        int t  = r & 3;
        int j = 0;
        while ((j + 1) * (j + 2) / 2 <= c && j < 7) j++;   // octet group
        int n = c - j * (j + 1) / 2;
        float v[4];
        #pragma unroll
        for (int q = 0; q < 4; q++) {
            int klocal = (q < 2) ? (2 * t + q) : (2 * t + 6 + q);  // 2t,2t+1,2t+8,2t+9
            if (c == 36) {                       // linear chunk
                int jc = kb * 16 + klocal;
                v[q] = 2.0f * w1[jc * kH + h];
            } else {
                int half = kb * 2 + (klocal >> 3);
                int i    = 8 * n + half;
                int jc   = 8 * j + (klocal & 7);
                if (jc > i)       v[q] = sw[i * 64 + jc] + sw[jc * 64 + i];
                else if (jc == i) v[q] = sw[i * 64 + jc];
                else              v[q] = 0.0f;   // below-diagonal padding
            }
        }
        uint32_t lo, hi;
        CVT_BF16X2(lo, v[0], v[1]);
        CVT_BF16X2(hi, v[2], v[3]);
        dst[c * 2048 + kb * 128 + t * 2 + hbase] = make_uint2(lo, hi);
    }
}

// ---------------------------------------------------------------------------
// one k16 block: octet = live pair half ODD; rows 8n+2KB, 8n+2KB+1 (via xqn).
// ab[mb][{Jlo.g, Jlo.g8, Jhi.g, Jhi.g8}]: aE = ab[mb][ODD*2 + {0,1}].
// ---------------------------------------------------------------------------
template<int ODD, int KB>
__device__ __forceinline__ void do_kb(
    const uint4* __restrict__ gBc, uint4 (&bfr)[4][2],
    const uint32_t (&ab)[2][4], const uint32_t* __restrict__ xqn,
    float (&acc)[2][4][4])
{
    uint4 s0 = *reinterpret_cast<const uint4*>(xqn + (2 * KB) * 128);
    uint4 s1 = *reinterpret_cast<const uint4*>(xqn + (2 * KB + 1) * 128);
    const uint4 lo = bfr[KB][0], hi = bfr[KB][1];
    bfr[KB][0] = gBc[1024 + KB * 64];          // prefetch next chunk's KB
    bfr[KB][1] = gBc[1024 + KB * 64 + 32];
    const uint32_t sv0[4] = { s0.x, s0.y, s0.z, s0.w };   // rows g,g8,g16,g24
    const uint32_t sv1[4] = { s1.x, s1.y, s1.z, s1.w };
    #pragma unroll
    for (int mb = 0; mb < 2; mb++) {
        const uint32_t aE0 = ab[mb][ODD * 2];      // rows g,   octet J
        const uint32_t aE1 = ab[mb][ODD * 2 + 1];  // rows g+8, octet J
        uint32_t t0, t1, t2, t3;
        HMUL2(t0, aE0, sv0[2 * mb]);       // k 0-7,  rows g    (scale i0)
        HMUL2(t1, aE1, sv0[2 * mb + 1]);   // k 0-7,  rows g+8
        HMUL2(t2, aE0, sv1[2 * mb]);       // k 8-15, rows g    (scale i1)
        HMUL2(t3, aE1, sv1[2 * mb + 1]);   // k 8-15, rows g+8
        MMA16816(acc[mb][0], t0, t1, t2, t3, lo.x, lo.y);
        MMA16816(acc[mb][1], t0, t1, t2, t3, lo.z, lo.w);
        MMA16816(acc[mb][2], t0, t1, t2, t3, hi.x, hi.y);
        MMA16816(acc[mb][3], t0, t1, t2, t3, hi.z, hi.w);
    }
}

// ---------------------------------------------------------------------------
// main fused kernel: 128-row M-tile per CTA, H=128 as N, 16 warps (4M x 4N),
// 1 CTA per SM, no barriers in the main loop, ~8 regs of live A
// ---------------------------------------------------------------------------
__global__ void __launch_bounds__(kThreads, 1)
rbm_main_kernel(const float* __restrict__ x,
                const float* __restrict__ bias,
                float* __restrict__ out) {
    extern __shared__ char smem_raw[];
    char* sm = (char*)((((uintptr_t)smem_raw) + 1023) & ~(uintptr_t)1023);
    const uint32_t sb = smem_u32(sm);
    const int tid = threadIdx.x;
    const int l   = tid & 31;
    const int w   = tid >> 5;
    const int g   = l >> 2;
    const int t4  = l & 3;
    const int wm  = (w >> 2) * 32;     // warp M offset (0,32,64,96)
    const int wn  = (w & 3) * 32;      // warp N offset (0,32,64,96)
    const int m0  = blockIdx.x * kMTile;

    float*    sbias = (float*)(sm + SM_BIAS);
    float*    spart = (float*)(sm + SM_PART);     // [m][4 wn-groups]
    uint32_t* xq    = (uint32_t*)(sm + SM_XQ);    // [j][32 grp][4 t] u32

    if (tid < kH) sbias[tid] = bias[tid];

    // --- x bf16 tile [m][j], 128B rows, SW128 swizzled (A ldmatrix source) ---
    {
        const float4* x4 = (const float4*)(x + (size_t)m0 * kV);
        #pragma unroll
        for (int e = tid; e < kMTile * 16; e += kThreads) {   // 128 rows * 16 f4
            int r = e >> 4, q = e & 15;
            float4 f = x4[e];
            uint32_t u0, u1;
            CVT_BF16X2(u0, f.x, f.y);
            CVT_BF16X2(u1, f.z, f.w);
            uint32_t off = (uint32_t)(r * 128 + q * 8);
            *(uint2*)(sm + SM_XT + SW128(off)) = make_uint2(u0, u1);
        }
    }
    // --- xq[j][grp][t] = bf16x2 broadcast of x[m0 + (grp>>3)*32 + (grp&7) + 8t][j]
    #pragma unroll
    for (int e = tid; e < kV * 32 * 4; e += kThreads) {   // 8192 entries
        int j   = e >> 7;
        int grp = (e >> 2) & 31;
        int t   = e & 3;
        int m   = (grp >> 3) * 32 + (grp & 7) + 8 * t;
        float v = x[(size_t)(m0 + m) * kV + j];
        uint32_t p;
        CVT_BF16X2(p, v, v);
        xq[e] = p;
    }

    // --- per-thread fragment pointer into g_wb (uint4 units) ---
    const uint4* gB = reinterpret_cast<const uint4*>(g_wb) + (w & 3) * 256 + l;

    // --- prologue: chunk 0 fragments into registers ---
    uint4 bfr[4][2];
    #pragma unroll
    for (int kb = 0; kb < 4; kb++) {
        bfr[kb][0] = gB[kb * 64];
        bfr[kb][1] = gB[kb * 64 + 32];
    }

    __syncthreads();   // x tiles + bias ready (only barrier before epilogue)

    float acc[2][4][4];
    #pragma unroll
    for (int a = 0; a < 2; a++)
    #pragma unroll
    for (int b = 0; b < 4; b++)
    #pragma unroll
    for (int c = 0; c < 4; c++) acc[a][b][c] = 0.0f;

    const int rb0 = wm + g;
    const uint32_t* xqg = xq + ((wm >> 2) + g) * 4;   // grp = (wm>>2)+g
    const uint4* gBc = gB;
    uint32_t ab[2][4];                                 // live octet pair
    const int q2 = l >> 3, rr = l & 7;

    // reload A octet pair (JJ, JJ+1), JJ even:
    // ab[mb] = {JJ.g, JJ.g8, JJ+1.g, JJ+1.g8}
    #define RELOAD_AB(JJ) do {                                                \
        _Pragma("unroll")                                                     \
        for (int mb = 0; mb < 2; mb++) {                                      \
            uint32_t off = (uint32_t)((wm + 16 * mb + (q2 & 1) * 8 + rr) * 128\
                                      + (((JJ) >> 1) * 16 + (q2 >> 1) * 8) * 2);\
            LDSM_X4(ab[mb][0], ab[mb][1], ab[mb][2], ab[mb][3],               \
                    sb + SM_XT + SW128(off));                                 \
        }                                                                     \
    } while (0)

    // group J: J+1 chunks, rows 8n..8n+7, octet J (compile-time parity)
    #define RUN_GROUP(J)                                                      \
        _Pragma("unroll 1")                                                   \
        for (int n = 0; n <= (J); n++) {                                      \
            const uint32_t* xqn = xqg + n * 1024;                             \
            do_kb<(J) & 1, 0>(gBc, bfr, ab, xqn, acc);                        \
            do_kb<(J) & 1, 1>(gBc, bfr, ab, xqn, acc);                        \
            do_kb<(J) & 1, 2>(gBc, bfr, ab, xqn, acc);                        \
            do_kb<(J) & 1, 3>(gBc, bfr, ab, xqn, acc);                        \
            gBc += 1024;                                                      \
        }

    RELOAD_AB(0); RUN_GROUP(0) RUN_GROUP(1)
    RELOAD_AB(2); RUN_GROUP(2) RUN_GROUP(3)
    RELOAD_AB(4); RUN_GROUP(4) RUN_GROUP(5)
    RELOAD_AB(6); RUN_GROUP(6) RUN_GROUP(7)
    #undef RUN_GROUP
    #undef RELOAD_AB

    // --- linear chunk (c = 36, scale = 1): A straight from XT per kb ---
    #pragma unroll
    for (int KB = 0; KB < 4; KB++) {
        const uint4 lo = bfr[KB][0], hi = bfr[KB][1];
        #pragma unroll
        for (int mb = 0; mb < 2; mb++) {
            uint32_t t0, t1, t2, t3;
            uint32_t off = (uint32_t)((wm + 16 * mb + (q2 & 1) * 8 + rr) * 128
                                      + (KB * 16 + (q2 >> 1) * 8) * 2);
            LDSM_X4(t0, t1, t2, t3, sb + SM_XT + SW128(off));
            MMA16816(acc[mb][0], t0, t1, t2, t3, lo.x, lo.y);
            MMA16816(acc[mb][1], t0, t1, t2, t3, lo.z, lo.w);
            MMA16816(acc[mb][2], t0, t1, t2, t3, hi.x, hi.y);
            MMA16816(acc[mb][3], t0, t1, t2, t3, hi.z, hi.w);
        }
    }

    // --- epilogue: a = bias + 0.5*acc; psi = prod cos(a) ---
    #pragma unroll
    for (int mb = 0; mb < 2; mb++) {
        float p0 = 1.0f, p1 = 1.0f;
        #pragma unroll
        for (int nb = 0; nb < 4; nb++) {
            int col = wn + nb * 8 + 2 * t4;
            #pragma unroll
            for (int cc = 0; cc < 2; cc++) {
                float bv = sbias[col + cc];
                p0 *= cos_poly(bv + 0.5f * acc[mb][nb][cc]);       // row g
                p1 *= cos_poly(bv + 0.5f * acc[mb][nb][2 + cc]);   // row g+8
            }
        }
        p0 *= __shfl_xor_sync(0xFFFFFFFFu, p0, 1);
        p0 *= __shfl_xor_sync(0xFFFFFFFFu, p0, 2);
        p1 *= __shfl_xor_sync(0xFFFFFFFFu, p1, 1);
        p1 *= __shfl_xor_sync(0xFFFFFFFFu, p1, 2);
        if (t4 == 0) {
            spart[(rb0 + 16 * mb) * 4 + (w & 3)]     = p0;
            spart[(rb0 + 16 * mb + 8) * 4 + (w & 3)] = p1;
        }
    }
    __syncthreads();
    if (tid < kMTile) {
        out[m0 + tid] = spart[tid * 4 + 0] * spart[tid * 4 + 1]
                      * spart[tid * 4 + 2] * spart[tid * 4 + 3];
    }
}

// ---------------------------------------------------------------------------
// launch
// ---------------------------------------------------------------------------
extern "C" void kernel_launch(void* const* d_in, const int* in_sizes, int n_in,
                              void* d_out, int out_size) {
    const float* x    = (const float*)d_in[0];   // (16384, 64)
    const float* w1   = (const float*)d_in[1];   // (64, 128)
    const float* w2   = (const float*)d_in[2];   // (128, 64, 64)
    const float* bias = (const float*)d_in[3];   // (128,)
    float* out = (float*)d_out;                  // (16384,)

    cudaFuncSetAttribute(rbm_main_kernel,
                         cudaFuncAttributeMaxDynamicSharedMemorySize, SMEM_TOTAL);

    prep_kernel<<<kH, 256>>>(w2, w1);            // one CTA per h
    rbm_main_kernel<<<16384 / kMTile, kThreads, SMEM_TOTAL>>>(x, bias, out);
}